// round 15
// baseline (speedup 1.0000x reference)
#include <cuda_runtime.h>
#include <cuda_bf16.h>
#include <stdint.h>

// Problem constants (from reference setup_inputs)
#define N_NODES 50000
#define C_IN    1536
#define C_HID   256
#define C_OUT   128
#define E_MAX   1600000

// ---------------------------------------------------------------------------
// Device-global scratch (no allocation allowed)
// ---------------------------------------------------------------------------
__device__ float4 g_h1 [N_NODES * C_HID / 4];   // GEMM1 out (f32)
__device__ float4 g_h2 [N_NODES * C_OUT / 4];   // GEMM2 out (f32)
__device__ float  g_dinv[N_NODES];

// CSR-by-dst edge structure (built per launch)
__device__ int    g_deg   [N_NODES];
__device__ int    g_eoff  [N_NODES + 1];
__device__ int    g_cursor[N_NODES];
__device__ int2   g_epack [E_MAX];              // {src, weight bits} per edge

// bf16 hi/lo splits (K-major weights; z from fused agg1)
__device__ __nv_bfloat16 g_zhi [N_NODES * C_HID];
__device__ __nv_bfloat16 g_zlo [N_NODES * C_HID];
__device__ __nv_bfloat16 g_w1hi[C_IN * C_HID];
__device__ __nv_bfloat16 g_w1lo[C_IN * C_HID];
__device__ __nv_bfloat16 g_w2hi[C_HID * C_OUT];
__device__ __nv_bfloat16 g_w2lo[C_HID * C_OUT];

// ---------------------------------------------------------------------------
// Weight splits: W1 and W2 in ONE launch (f32 -> hi/lo bf16, K-major)
// ---------------------------------------------------------------------------
#define W1_N4 (C_IN * C_HID / 4)    // 98304
#define W2_N4 (C_HID * C_OUT / 4)   // 8192

__global__ void split_weights_kernel(const float* __restrict__ W1,
                                     const float* __restrict__ W2) {
    int i = blockIdx.x * blockDim.x + threadIdx.x;
    if (i >= W1_N4 + W2_N4) return;
    const float4* in;
    __nv_bfloat16 *hi, *lo;
    int j;
    if (i < W1_N4) { in = (const float4*)W1; hi = g_w1hi; lo = g_w1lo; j = i; }
    else           { in = (const float4*)W2; hi = g_w2hi; lo = g_w2lo; j = i - W1_N4; }
    float4 v = in[j];
    float f[4] = {v.x, v.y, v.z, v.w};
    __nv_bfloat16 h[4], l[4];
#pragma unroll
    for (int t = 0; t < 4; ++t) {
        h[t] = __float2bfloat16_rn(f[t]);
        l[t] = __float2bfloat16_rn(f[t] - __bfloat162float(h[t]));
    }
    ((__nv_bfloat162*)hi)[2 * j]     = __nv_bfloat162(h[0], h[1]);
    ((__nv_bfloat162*)hi)[2 * j + 1] = __nv_bfloat162(h[2], h[3]);
    ((__nv_bfloat162*)lo)[2 * j]     = __nv_bfloat162(l[0], l[1]);
    ((__nv_bfloat162*)lo)[2 * j + 1] = __nv_bfloat162(l[2], l[3]);
}

// ---------------------------------------------------------------------------
// degree histogram
// ---------------------------------------------------------------------------
__global__ void zero_deg_kernel() {
    int i = blockIdx.x * blockDim.x + threadIdx.x;
    if (i < N_NODES) g_deg[i] = 0;
}

__global__ void deg_accum_kernel(const int* __restrict__ dst, int E) {
    int i = blockIdx.x * blockDim.x + threadIdx.x;
    if (i < E) {
        unsigned d = (unsigned)dst[i];
        if (d < N_NODES) atomicAdd(&g_deg[d], 1);
    }
}

// ---------------------------------------------------------------------------
// Single-block exclusive scan of g_deg -> g_eoff / g_cursor; also dinv
// ---------------------------------------------------------------------------
#define SCAN_T 1024
__global__ __launch_bounds__(SCAN_T) void scan_kernel() {
    __shared__ int sh[SCAN_T];
    const int tid = threadIdx.x;
    const int PER = (N_NODES + SCAN_T - 1) / SCAN_T;
    const int base = tid * PER;
    int s = 0;
    for (int j = 0; j < PER; ++j) {
        int i = base + j;
        if (i < N_NODES) s += g_deg[i];
    }
    sh[tid] = s;
    __syncthreads();
    for (int off = 1; off < SCAN_T; off <<= 1) {
        int v = (tid >= off) ? sh[tid - off] : 0;
        __syncthreads();
        sh[tid] += v;
        __syncthreads();
    }
    int running = sh[tid] - s;
    for (int j = 0; j < PER; ++j) {
        int i = base + j;
        if (i < N_NODES) {
            int d = g_deg[i];
            g_eoff[i]   = running;
            g_cursor[i] = running;
            g_dinv[i]   = rsqrtf((float)(d + 1));   // +1 self-loop
            running += d;
        }
    }
    if (tid == SCAN_T - 1) g_eoff[N_NODES] = sh[SCAN_T - 1];
}

__global__ void bucket_kernel(const int* __restrict__ src,
                              const int* __restrict__ dst, int E) {
    int e = blockIdx.x * blockDim.x + threadIdx.x;
    if (e >= E) return;
    unsigned s = (unsigned)src[e];
    unsigned d = (unsigned)dst[e];
    if (s >= N_NODES || d >= N_NODES) return;
    int pos = atomicAdd(&g_cursor[d], 1);
    if (pos < E_MAX) {
        float w = g_dinv[s] * g_dinv[d];
        g_epack[pos] = make_int2((int)s, __float_as_int(w));
    }
}

// ---------------------------------------------------------------------------
// PTX helpers
// ---------------------------------------------------------------------------
__device__ __forceinline__ void mma_bf16(float c[4], const uint32_t a[4],
                                         const uint32_t b[2]) {
    asm volatile(
        "mma.sync.aligned.m16n8k16.row.col.f32.bf16.bf16.f32 "
        "{%0,%1,%2,%3}, {%4,%5,%6,%7}, {%8,%9}, {%0,%1,%2,%3};\n"
        : "+f"(c[0]), "+f"(c[1]), "+f"(c[2]), "+f"(c[3])
        : "r"(a[0]), "r"(a[1]), "r"(a[2]), "r"(a[3]), "r"(b[0]), "r"(b[1]));
}

__device__ __forceinline__ void ldsm_x4(uint32_t r[4], uint32_t addr) {
    asm volatile("ldmatrix.sync.aligned.m8n8.x4.shared.b16 {%0,%1,%2,%3}, [%4];"
                 : "=r"(r[0]), "=r"(r[1]), "=r"(r[2]), "=r"(r[3]) : "r"(addr));
}

__device__ __forceinline__ void ldsm_x4_t(uint32_t r[4], uint32_t addr) {
    asm volatile("ldmatrix.sync.aligned.m8n8.x4.trans.shared.b16 {%0,%1,%2,%3}, [%4];"
                 : "=r"(r[0]), "=r"(r[1]), "=r"(r[2]), "=r"(r[3]) : "r"(addr));
}

__device__ __forceinline__ void cp_async16(uint32_t saddr, const void* g, int srcbytes) {
    asm volatile("cp.async.cg.shared.global [%0], [%1], 16, %2;"
                 :: "r"(saddr), "l"(g), "r"(srcbytes));
}

__device__ __forceinline__ void sts_v2(uint32_t saddr, uint32_t a, uint32_t b) {
    asm volatile("st.shared.v2.b32 [%0], {%1, %2};" :: "r"(saddr), "r"(a), "r"(b));
}

__device__ __forceinline__ uint32_t pack_bf16x2(__nv_bfloat16 a, __nv_bfloat16 b) {
    __nv_bfloat162 p(a, b);
    return *(uint32_t*)&p;
}

// ---------------------------------------------------------------------------
// Unified split-bf16 tensor-core GEMM.  C[M,BNF] = A[M,K] @ B[K,BNF].
// 3-term: Ah*Bh + Ah*Bl + Al*Bh, term-outermost MMA order (RAW-chain free).
// GEMM1: MI=2, BN=256 (full width, grid.y=1) — amortizes B-fragment smem
// reads over 2x tensor work (smem-BW-bound ceiling 55% -> 71%).
// GEMM2: MI=2, BN=128 — same reasoning (35% -> 55%).
// MODE 0: A = X (f32, inline hi/lo split via LDG->STS), B = W1 splits, C = g_h1
// MODE 1: A = z splits (cp.async),                      B = W2 splits, C = g_h2
// ---------------------------------------------------------------------------
template <int MI, int BN, int KDIM, int MODE, int BK>
__global__ __launch_bounds__(256, 2) void mma_gemm(const float* __restrict__ X, int M) {
    constexpr int BM   = MI * 32;
    constexpr int AST  = BK * 2 + 16;          // A smem row stride (bytes)
    constexpr int BROW = BN * 2 + 16;          // B smem row stride (bytes)
    constexpr int A_STAGE = 2 * BM * AST;      // hi+lo
    constexpr int B_STAGE = 2 * BK * BROW;
    constexpr int NT  = BN / 32;               // n8-tile pairs per warp
    constexpr int KT  = KDIM / BK;
    constexpr int KS  = BK / 16;               // k16 sub-steps per tile
    constexpr int BNF = MODE ? C_OUT : C_HID;

    const __nv_bfloat16* Bh = MODE ? g_w2hi : g_w1hi;
    const __nv_bfloat16* Bl = MODE ? g_w2lo : g_w1lo;
    float*               C  = MODE ? (float*)g_h2 : (float*)g_h1;

    extern __shared__ char smem[];
    uint32_t sA = (uint32_t)__cvta_generic_to_shared(smem);
    uint32_t sB = sA + 2 * A_STAGE;

    const int tid = threadIdx.x, lane = tid & 31, warp = tid >> 5;
    const int warpM = warp & 1, warpN = warp >> 1;
    const int g = lane >> 2, t4 = lane & 3;
    const int rowBase = blockIdx.x * BM;
    const int colBase = blockIdx.y * BN;

    float acc[MI][NT][4] = {};

    constexpr int BK4 = BK / 4;                // f32 16B chunks per A row
    constexpr int AC  = (BM * BK4) / 256;      // per-thread A chunks (MODE 0)
    float4 areg[AC > 0 ? AC : 1];

    auto ldgA = [&](int kt) {
        if constexpr (MODE == 0) {
            const int k0 = kt * BK;
#pragma unroll
            for (int it = 0; it < AC; ++it) {
                int idx = tid + it * 256;
                int row = idx / BK4;
                int c4  = idx % BK4;
                int grow = rowBase + row;
                if (grow >= M) grow = M - 1;
                areg[it] = *(const float4*)(X + (size_t)grow * KDIM + k0 + c4 * 4);
            }
        }
    };

    auto stsA = [&](int s) {
        if constexpr (MODE == 0) {
#pragma unroll
            for (int it = 0; it < AC; ++it) {
                int idx = tid + it * 256;
                int row = idx / BK4;
                int c4  = idx % BK4;
                float f[4] = {areg[it].x, areg[it].y, areg[it].z, areg[it].w};
                __nv_bfloat16 h[4], l[4];
#pragma unroll
                for (int j = 0; j < 4; ++j) {
                    h[j] = __float2bfloat16_rn(f[j]);
                    l[j] = __float2bfloat16_rn(f[j] - __bfloat162float(h[j]));
                }
                uint32_t base = sA + s * A_STAGE + row * AST + c4 * 8;
                sts_v2(base,            pack_bf16x2(h[0], h[1]), pack_bf16x2(h[2], h[3]));
                sts_v2(base + BM * AST, pack_bf16x2(l[0], l[1]), pack_bf16x2(l[2], l[3]));
            }
        }
    };

    auto stageA_async = [&](int kt, int s) {
        if constexpr (MODE == 1) {
            const int k0 = kt * BK;
            constexpr int BK8 = BK / 8;
            constexpr int ACH = 2 * BM * BK8;
#pragma unroll
            for (int it = 0; it < ACH / 256; ++it) {
                int idx = tid + it * 256;
                int hl = idx / (ACH / 2);
                int cc = idx % (ACH / 2);
                int row = cc / BK8, kc = cc % BK8;
                int grow = rowBase + row;
                int sz = (grow < M) ? 16 : 0;
                if (grow >= M) grow = M - 1;
                const __nv_bfloat16* src =
                    (hl ? g_zlo : g_zhi) + (size_t)grow * KDIM + k0 + kc * 8;
                cp_async16(sA + s * A_STAGE + hl * (BM * AST) + row * AST + kc * 16, src, sz);
            }
        }
    };

    auto stageB = [&](int kt, int s) {
        const int k0 = kt * BK;
        constexpr int BCH = 2 * BK * (BN / 8);
#pragma unroll
        for (int it = 0; it < BCH / 256; ++it) {
            int c = tid + it * 256;
            int hl = c / (BCH / 2);
            int cc = c % (BCH / 2);
            int row = cc / (BN / 8), nc = cc % (BN / 8);
            const __nv_bfloat16* src =
                (hl ? Bl : Bh) + (size_t)(k0 + row) * BNF + colBase + nc * 8;
            cp_async16(sB + s * B_STAGE + hl * (BK * BROW) + row * BROW + nc * 16, src, 16);
        }
        asm volatile("cp.async.commit_group;");
    };

    ldgA(0);
    stageA_async(0, 0);
    stageB(0, 0);
    for (int kt = 0; kt < KT; ++kt) {
        const int s = kt & 1;
        stsA(s);
        if (kt + 1 < KT) {
            ldgA(kt + 1);
            stageA_async(kt + 1, s ^ 1);
            stageB(kt + 1, s ^ 1);
            asm volatile("cp.async.wait_group 1;");
        } else {
            asm volatile("cp.async.wait_group 0;");
        }
        __syncthreads();

        const int q = lane >> 3;
#pragma unroll
        for (int ks = 0; ks < KS; ++ks) {
            uint32_t a[MI][2][4];
#pragma unroll
            for (int mi = 0; mi < MI; ++mi) {
                int row  = warpM * (MI * 16) + mi * 16 + (q & 1) * 8 + (lane & 7);
                int colb = (ks * 16 + (q >> 1) * 8) * 2;
#pragma unroll
                for (int hl = 0; hl < 2; ++hl)
                    ldsm_x4(a[mi][hl], sA + s * A_STAGE + hl * (BM * AST) + row * AST + colb);
            }
#pragma unroll
            for (int np = 0; np < NT / 2; ++np) {
                uint32_t bq[2][4];
                int krow = ks * 16 + (q & 1) * 8 + (lane & 7);
                int ncol = warpN * (BN / 4) + np * 16 + (q >> 1) * 8;
#pragma unroll
                for (int hl = 0; hl < 2; ++hl)
                    ldsm_x4_t(bq[hl], sB + s * B_STAGE + hl * (BK * BROW) + krow * BROW + ncol * 2);
#pragma unroll
                for (int term = 0; term < 3; ++term) {
                    const int ahl = (term == 2) ? 1 : 0;
                    const int bhl = (term == 1) ? 1 : 0;
#pragma unroll
                    for (int half = 0; half < 2; ++half) {
                        uint32_t bb[2] = {bq[bhl][half * 2], bq[bhl][half * 2 + 1]};
                        const int nt = np * 2 + half;
#pragma unroll
                        for (int mi = 0; mi < MI; ++mi)
                            mma_bf16(acc[mi][nt], a[mi][ahl], bb);
                    }
                }
            }
        }
        __syncthreads();
    }

    // epilogue
#pragma unroll
    for (int mi = 0; mi < MI; ++mi)
#pragma unroll
        for (int nt = 0; nt < NT; ++nt) {
            int col = colBase + warpN * (BN / 4) + nt * 8 + t4 * 2;
            int r0  = rowBase + warpM * (MI * 16) + mi * 16 + g;
            if (r0 < M)
                *(float2*)(C + (size_t)r0 * BNF + col) = make_float2(acc[mi][nt][0], acc[mi][nt][1]);
            int r1 = r0 + 8;
            if (r1 < M)
                *(float2*)(C + (size_t)r1 * BNF + col) = make_float2(acc[mi][nt][2], acc[mi][nt][3]);
        }
}

// ---------------------------------------------------------------------------
// Layer-1 gather aggregation (warp per node, C=256) + bias + relu + bf16 split
// ---------------------------------------------------------------------------
__global__ __launch_bounds__(256) void gather_agg1_kernel(const float* __restrict__ b1) {
    int node = (blockIdx.x * blockDim.x + threadIdx.x) >> 5;
    int lane = threadIdx.x & 31;
    if (node >= N_NODES) return;

    const float4* h = g_h1;
    float di = g_dinv[node];
    float ws = di * di;
    size_t rb = (size_t)node * 64;
    float4 a0 = h[rb + lane];
    float4 a1 = h[rb + 32 + lane];
    a0.x *= ws; a0.y *= ws; a0.z *= ws; a0.w *= ws;
    a1.x *= ws; a1.y *= ws; a1.z *= ws; a1.w *= ws;

    int beg = g_eoff[node], end = g_eoff[node + 1];
    int k = beg;
    for (; k + 2 <= end; k += 2) {
        int2 e0 = g_epack[k], e1 = g_epack[k + 1];
        float w0 = __int_as_float(e0.y), w1 = __int_as_float(e1.y);
        size_t r0 = (size_t)e0.x * 64, r1 = (size_t)e1.x * 64;
        float4 v00 = h[r0 + lane], v01 = h[r0 + 32 + lane];
        float4 v10 = h[r1 + lane], v11 = h[r1 + 32 + lane];
        a0.x += v00.x * w0; a0.y += v00.y * w0; a0.z += v00.z * w0; a0.w += v00.w * w0;
        a1.x += v01.x * w0; a1.y += v01.y * w0; a1.z += v01.z * w0; a1.w += v01.w * w0;
        a0.x += v10.x * w1; a0.y += v10.y * w1; a0.z += v10.z * w1; a0.w += v10.w * w1;
        a1.x += v11.x * w1; a1.y += v11.y * w1; a1.z += v11.z * w1; a1.w += v11.w * w1;
    }
    if (k < end) {
        int2 e0 = g_epack[k];
        float w0 = __int_as_float(e0.y);
        size_t r0 = (size_t)e0.x * 64;
        float4 v00 = h[r0 + lane], v01 = h[r0 + 32 + lane];
        a0.x += v00.x * w0; a0.y += v00.y * w0; a0.z += v00.z * w0; a0.w += v00.w * w0;
        a1.x += v01.x * w0; a1.y += v01.y * w0; a1.z += v01.z * w0; a1.w += v01.w * w0;
    }

    float4 bb0 = ((const float4*)b1)[lane];
    float4 bb1 = ((const float4*)b1)[lane + 32];
    float f0[4] = {fmaxf(a0.x + bb0.x, 0.f), fmaxf(a0.y + bb0.y, 0.f),
                   fmaxf(a0.z + bb0.z, 0.f), fmaxf(a0.w + bb0.w, 0.f)};
    float f1[4] = {fmaxf(a1.x + bb1.x, 0.f), fmaxf(a1.y + bb1.y, 0.f),
                   fmaxf(a1.z + bb1.z, 0.f), fmaxf(a1.w + bb1.w, 0.f)};

    __nv_bfloat162* zh = (__nv_bfloat162*)(g_zhi + (size_t)node * C_HID);
    __nv_bfloat162* zl = (__nv_bfloat162*)(g_zlo + (size_t)node * C_HID);
#pragma unroll
    for (int half = 0; half < 2; ++half) {
        float* f = half ? f1 : f0;
        int idx = 2 * (lane + half * 32);
        __nv_bfloat16 h0 = __float2bfloat16_rn(f[0]);
        __nv_bfloat16 h1v = __float2bfloat16_rn(f[1]);
        __nv_bfloat16 h2v = __float2bfloat16_rn(f[2]);
        __nv_bfloat16 h3 = __float2bfloat16_rn(f[3]);
        zh[idx]     = __nv_bfloat162(h0, h1v);
        zh[idx + 1] = __nv_bfloat162(h2v, h3);
        zl[idx]     = __nv_bfloat162(__float2bfloat16_rn(f[0] - __bfloat162float(h0)),
                                     __float2bfloat16_rn(f[1] - __bfloat162float(h1v)));
        zl[idx + 1] = __nv_bfloat162(__float2bfloat16_rn(f[2] - __bfloat162float(h2v)),
                                     __float2bfloat16_rn(f[3] - __bfloat162float(h3)));
    }
}

// ---------------------------------------------------------------------------
// Layer-2 gather aggregation + bias + row-normalize (warp per node, C=128)
// ---------------------------------------------------------------------------
__global__ __launch_bounds__(256) void gather_agg2_kernel(const float* __restrict__ b2,
                                                          float* __restrict__ out) {
    int node = (blockIdx.x * blockDim.x + threadIdx.x) >> 5;
    int lane = threadIdx.x & 31;
    if (node >= N_NODES) return;

    const float4* h = g_h2;
    float di = g_dinv[node];
    float ws = di * di;
    float4 a = h[(size_t)node * 32 + lane];
    a.x *= ws; a.y *= ws; a.z *= ws; a.w *= ws;

    int beg = g_eoff[node], end = g_eoff[node + 1];
    int k = beg;
    for (; k + 2 <= end; k += 2) {
        int2 e0 = g_epack[k], e1 = g_epack[k + 1];
        float w0 = __int_as_float(e0.y), w1 = __int_as_float(e1.y);
        float4 v0 = h[(size_t)e0.x * 32 + lane];
        float4 v1 = h[(size_t)e1.x * 32 + lane];
        a.x += v0.x * w0; a.y += v0.y * w0; a.z += v0.z * w0; a.w += v0.w * w0;
        a.x += v1.x * w1; a.y += v1.y * w1; a.z += v1.z * w1; a.w += v1.w * w1;
    }
    if (k < end) {
        int2 e0 = g_epack[k];
        float w0 = __int_as_float(e0.y);
        float4 v0 = h[(size_t)e0.x * 32 + lane];
        a.x += v0.x * w0; a.y += v0.y * w0; a.z += v0.z * w0; a.w += v0.w * w0;
    }

    float4 bb = ((const float4*)b2)[lane];
    a.x += bb.x; a.y += bb.y; a.z += bb.z; a.w += bb.w;
    float s = a.x * a.x + a.y * a.y + a.z * a.z + a.w * a.w;
#pragma unroll
    for (int m = 16; m > 0; m >>= 1) s += __shfl_xor_sync(0xffffffffu, s, m);
    float inv = 1.0f / fmaxf(sqrtf(s), 1e-12f);
    a.x *= inv; a.y *= inv; a.z *= inv; a.w *= inv;
    ((float4*)out)[(size_t)node * 32 + lane] = a;
}

// ---------------------------------------------------------------------------
// Launch: CSR || GEMM1; serial agg1 -> GEMM2 -> agg2.
// ---------------------------------------------------------------------------
extern "C" void kernel_launch(void* const* d_in, const int* in_sizes, int n_in,
                              void* d_out, int out_size) {
    const float* x  = (const float*)d_in[0];
    const int*   ei = (const int*)d_in[1];      // int32
    const float* W1 = (const float*)d_in[2];
    const float* b1 = (const float*)d_in[3];
    const float* W2 = (const float*)d_in[4];
    const float* b2 = (const float*)d_in[5];
    float* out = (float*)d_out;

    const int E = in_sizes[1] / 2;
    const int* src = ei;
    const int* dst = ei + E;

    // GEMM1: MI=2,BN=256,BK=32 -> 2*(2*64*80 + 2*32*528) = 88064
    // GEMM2: MI=2,BN=128,BK=32 -> 2*(2*64*80 + 2*32*272) = 55296
    constexpr int SMEM1 = 2 * (2 * 64 * (32 * 2 + 16) + 2 * 32 * (256 * 2 + 16));
    constexpr int SMEM2 = 2 * (2 * 64 * (32 * 2 + 16) + 2 * 32 * (128 * 2 + 16));

    static cudaStream_t s2 = nullptr;
    static cudaEvent_t  evF = nullptr, evJ = nullptr;
    static bool init_done = false;
    if (!init_done) {
        cudaFuncSetAttribute((const void*)mma_gemm<2, 256, C_IN, 0, 32>,
                             cudaFuncAttributeMaxDynamicSharedMemorySize, SMEM1);
        cudaFuncSetAttribute((const void*)mma_gemm<2, 128, C_HID, 1, 32>,
                             cudaFuncAttributeMaxDynamicSharedMemorySize, SMEM2);
        cudaStreamCreateWithFlags(&s2, cudaStreamNonBlocking);
        cudaEventCreateWithFlags(&evF, cudaEventDisableTiming);
        cudaEventCreateWithFlags(&evJ, cudaEventDisableTiming);
        init_done = true;
    }

    // fork: CSR build chain on s2 (disjoint buffers from GEMM1 path)
    cudaEventRecord(evF, 0);
    cudaStreamWaitEvent(s2, evF, 0);
    zero_deg_kernel<<<(N_NODES + 255) / 256, 256, 0, s2>>>();
    deg_accum_kernel<<<(E + 255) / 256, 256, 0, s2>>>(dst, E);
    scan_kernel<<<1, SCAN_T, 0, s2>>>();
    bucket_kernel<<<(E + 255) / 256, 256, 0, s2>>>(src, dst, E);
    cudaEventRecord(evJ, s2);

    // main stream: weight splits + GEMM1 (concurrent with CSR build)
    split_weights_kernel<<<(W1_N4 + W2_N4 + 255) / 256, 256>>>(W1, W2);
    {
        dim3 grid((N_NODES + 63) / 64, 1);     // BN=256 covers full width
        mma_gemm<2, 256, C_IN, 0, 32><<<grid, 256, SMEM1>>>(x, N_NODES);
    }

    // join: agg1 needs both g_h1 (main) and CSR (s2)
    cudaStreamWaitEvent(0, evJ, 0);

    // serial agg1 -> GEMM2 -> agg2
    gather_agg1_kernel<<<(N_NODES * 32 + 255) / 256, 256>>>(b1);
    {
        dim3 grid((N_NODES + 63) / 64, 1);     // BM=64
        mma_gemm<2, 128, C_HID, 1, 32><<<grid, 256, SMEM2>>>(nullptr, N_NODES);
    }
    gather_agg2_kernel<<<(N_NODES * 32 + 255) / 256, 256>>>(b2, out);
}

// round 16
// speedup vs baseline: 1.0397x; 1.0397x over previous
#include <cuda_runtime.h>
#include <cuda_bf16.h>
#include <stdint.h>

// Problem constants (from reference setup_inputs)
#define N_NODES 50000
#define C_IN    1536
#define C_HID   256
#define C_OUT   128
#define E_MAX   1600000

// ---------------------------------------------------------------------------
// Device-global scratch (no allocation allowed)
// ---------------------------------------------------------------------------
__device__ float4 g_h1 [N_NODES * C_HID / 4];   // GEMM1 out (f32)
__device__ float4 g_h2 [N_NODES * C_OUT / 4];   // GEMM2 out (f32)
__device__ float  g_dinv[N_NODES];

// CSR-by-dst edge structure (built per launch)
__device__ int    g_deg   [N_NODES];
__device__ int    g_eoff  [N_NODES + 1];
__device__ int    g_cursor[N_NODES];
__device__ int2   g_epack [E_MAX];              // {src, weight bits} per edge

// bf16 hi/lo splits (K-major weights; z from fused agg1)
__device__ __nv_bfloat16 g_zhi [N_NODES * C_HID];
__device__ __nv_bfloat16 g_zlo [N_NODES * C_HID];
__device__ __nv_bfloat16 g_w1hi[C_IN * C_HID];
__device__ __nv_bfloat16 g_w1lo[C_IN * C_HID];
__device__ __nv_bfloat16 g_w2hi[C_HID * C_OUT];
__device__ __nv_bfloat16 g_w2lo[C_HID * C_OUT];

// ---------------------------------------------------------------------------
// Weight splits: W1 and W2 in ONE launch (f32 -> hi/lo bf16, K-major)
// ---------------------------------------------------------------------------
#define W1_N4 (C_IN * C_HID / 4)    // 98304
#define W2_N4 (C_HID * C_OUT / 4)   // 8192

__global__ void split_weights_kernel(const float* __restrict__ W1,
                                     const float* __restrict__ W2) {
    int i = blockIdx.x * blockDim.x + threadIdx.x;
    if (i >= W1_N4 + W2_N4) return;
    const float4* in;
    __nv_bfloat16 *hi, *lo;
    int j;
    if (i < W1_N4) { in = (const float4*)W1; hi = g_w1hi; lo = g_w1lo; j = i; }
    else           { in = (const float4*)W2; hi = g_w2hi; lo = g_w2lo; j = i - W1_N4; }
    float4 v = in[j];
    float f[4] = {v.x, v.y, v.z, v.w};
    __nv_bfloat16 h[4], l[4];
#pragma unroll
    for (int t = 0; t < 4; ++t) {
        h[t] = __float2bfloat16_rn(f[t]);
        l[t] = __float2bfloat16_rn(f[t] - __bfloat162float(h[t]));
    }
    ((__nv_bfloat162*)hi)[2 * j]     = __nv_bfloat162(h[0], h[1]);
    ((__nv_bfloat162*)hi)[2 * j + 1] = __nv_bfloat162(h[2], h[3]);
    ((__nv_bfloat162*)lo)[2 * j]     = __nv_bfloat162(l[0], l[1]);
    ((__nv_bfloat162*)lo)[2 * j + 1] = __nv_bfloat162(l[2], l[3]);
}

// ---------------------------------------------------------------------------
// degree histogram
// ---------------------------------------------------------------------------
__global__ void zero_deg_kernel() {
    int i = blockIdx.x * blockDim.x + threadIdx.x;
    if (i < N_NODES) g_deg[i] = 0;
}

__global__ void deg_accum_kernel(const int* __restrict__ dst, int E) {
    int i = blockIdx.x * blockDim.x + threadIdx.x;
    if (i < E) {
        unsigned d = (unsigned)dst[i];
        if (d < N_NODES) atomicAdd(&g_deg[d], 1);
    }
}

// ---------------------------------------------------------------------------
// Single-block exclusive scan of g_deg -> g_eoff / g_cursor; also dinv
// ---------------------------------------------------------------------------
#define SCAN_T 1024
__global__ __launch_bounds__(SCAN_T) void scan_kernel() {
    __shared__ int sh[SCAN_T];
    const int tid = threadIdx.x;
    const int PER = (N_NODES + SCAN_T - 1) / SCAN_T;
    const int base = tid * PER;
    int s = 0;
    for (int j = 0; j < PER; ++j) {
        int i = base + j;
        if (i < N_NODES) s += g_deg[i];
    }
    sh[tid] = s;
    __syncthreads();
    for (int off = 1; off < SCAN_T; off <<= 1) {
        int v = (tid >= off) ? sh[tid - off] : 0;
        __syncthreads();
        sh[tid] += v;
        __syncthreads();
    }
    int running = sh[tid] - s;
    for (int j = 0; j < PER; ++j) {
        int i = base + j;
        if (i < N_NODES) {
            int d = g_deg[i];
            g_eoff[i]   = running;
            g_cursor[i] = running;
            g_dinv[i]   = rsqrtf((float)(d + 1));   // +1 self-loop
            running += d;
        }
    }
    if (tid == SCAN_T - 1) g_eoff[N_NODES] = sh[SCAN_T - 1];
}

__global__ void bucket_kernel(const int* __restrict__ src,
                              const int* __restrict__ dst, int E) {
    int e = blockIdx.x * blockDim.x + threadIdx.x;
    if (e >= E) return;
    unsigned s = (unsigned)src[e];
    unsigned d = (unsigned)dst[e];
    if (s >= N_NODES || d >= N_NODES) return;
    int pos = atomicAdd(&g_cursor[d], 1);
    if (pos < E_MAX) {
        float w = g_dinv[s] * g_dinv[d];
        g_epack[pos] = make_int2((int)s, __float_as_int(w));
    }
}

// ---------------------------------------------------------------------------
// PTX helpers
// ---------------------------------------------------------------------------
__device__ __forceinline__ void mma_bf16(float c[4], const uint32_t a[4],
                                         const uint32_t b[2]) {
    asm volatile(
        "mma.sync.aligned.m16n8k16.row.col.f32.bf16.bf16.f32 "
        "{%0,%1,%2,%3}, {%4,%5,%6,%7}, {%8,%9}, {%0,%1,%2,%3};\n"
        : "+f"(c[0]), "+f"(c[1]), "+f"(c[2]), "+f"(c[3])
        : "r"(a[0]), "r"(a[1]), "r"(a[2]), "r"(a[3]), "r"(b[0]), "r"(b[1]));
}

__device__ __forceinline__ void ldsm_x4(uint32_t r[4], uint32_t addr) {
    asm volatile("ldmatrix.sync.aligned.m8n8.x4.shared.b16 {%0,%1,%2,%3}, [%4];"
                 : "=r"(r[0]), "=r"(r[1]), "=r"(r[2]), "=r"(r[3]) : "r"(addr));
}

__device__ __forceinline__ void ldsm_x4_t(uint32_t r[4], uint32_t addr) {
    asm volatile("ldmatrix.sync.aligned.m8n8.x4.trans.shared.b16 {%0,%1,%2,%3}, [%4];"
                 : "=r"(r[0]), "=r"(r[1]), "=r"(r[2]), "=r"(r[3]) : "r"(addr));
}

__device__ __forceinline__ void cp_async16(uint32_t saddr, const void* g, int srcbytes) {
    asm volatile("cp.async.cg.shared.global [%0], [%1], 16, %2;"
                 :: "r"(saddr), "l"(g), "r"(srcbytes));
}

__device__ __forceinline__ void sts_v2(uint32_t saddr, uint32_t a, uint32_t b) {
    asm volatile("st.shared.v2.b32 [%0], {%1, %2};" :: "r"(saddr), "r"(a), "r"(b));
}

__device__ __forceinline__ uint32_t pack_bf16x2(__nv_bfloat16 a, __nv_bfloat16 b) {
    __nv_bfloat162 p(a, b);
    return *(uint32_t*)&p;
}

// ---------------------------------------------------------------------------
// Unified split-bf16 tensor-core GEMM (round-14 proven config).
// 3-term: Ah*Bh + Ah*Bl + Al*Bh, term-outermost MMA order (RAW-chain free).
// GEMM1: MI=2, BN=128, BK=32.  GEMM2: MI=1, BN=128, BK=32.
// MODE 0: A = X (f32, inline hi/lo split via LDG->STS), B = W1 splits, C = g_h1
// MODE 1: A = z splits (cp.async),                      B = W2 splits, C = g_h2
// ---------------------------------------------------------------------------
template <int MI, int BN, int KDIM, int MODE, int BK>
__global__ __launch_bounds__(256, 2) void mma_gemm(const float* __restrict__ X, int M) {
    constexpr int BM   = MI * 32;
    constexpr int AST  = BK * 2 + 16;          // A smem row stride (bytes)
    constexpr int BROW = BN * 2 + 16;          // B smem row stride (bytes)
    constexpr int A_STAGE = 2 * BM * AST;      // hi+lo
    constexpr int B_STAGE = 2 * BK * BROW;
    constexpr int NT  = BN / 32;               // n8-tile pairs per warp
    constexpr int KT  = KDIM / BK;
    constexpr int KS  = BK / 16;               // k16 sub-steps per tile
    constexpr int BNF = MODE ? C_OUT : C_HID;

    const __nv_bfloat16* Bh = MODE ? g_w2hi : g_w1hi;
    const __nv_bfloat16* Bl = MODE ? g_w2lo : g_w1lo;
    float*               C  = MODE ? (float*)g_h2 : (float*)g_h1;

    extern __shared__ char smem[];
    uint32_t sA = (uint32_t)__cvta_generic_to_shared(smem);
    uint32_t sB = sA + 2 * A_STAGE;

    const int tid = threadIdx.x, lane = tid & 31, warp = tid >> 5;
    const int warpM = warp & 1, warpN = warp >> 1;
    const int g = lane >> 2, t4 = lane & 3;
    const int rowBase = blockIdx.x * BM;
    const int colBase = blockIdx.y * BN;

    float acc[MI][NT][4] = {};

    constexpr int BK4 = BK / 4;                // f32 16B chunks per A row
    constexpr int AC  = (BM * BK4) / 256;      // per-thread A chunks (MODE 0)
    float4 areg[AC > 0 ? AC : 1];

    auto ldgA = [&](int kt) {
        if constexpr (MODE == 0) {
            const int k0 = kt * BK;
#pragma unroll
            for (int it = 0; it < AC; ++it) {
                int idx = tid + it * 256;
                int row = idx / BK4;
                int c4  = idx % BK4;
                int grow = rowBase + row;
                if (grow >= M) grow = M - 1;
                areg[it] = *(const float4*)(X + (size_t)grow * KDIM + k0 + c4 * 4);
            }
        }
    };

    auto stsA = [&](int s) {
        if constexpr (MODE == 0) {
#pragma unroll
            for (int it = 0; it < AC; ++it) {
                int idx = tid + it * 256;
                int row = idx / BK4;
                int c4  = idx % BK4;
                float f[4] = {areg[it].x, areg[it].y, areg[it].z, areg[it].w};
                __nv_bfloat16 h[4], l[4];
#pragma unroll
                for (int j = 0; j < 4; ++j) {
                    h[j] = __float2bfloat16_rn(f[j]);
                    l[j] = __float2bfloat16_rn(f[j] - __bfloat162float(h[j]));
                }
                uint32_t base = sA + s * A_STAGE + row * AST + c4 * 8;
                sts_v2(base,            pack_bf16x2(h[0], h[1]), pack_bf16x2(h[2], h[3]));
                sts_v2(base + BM * AST, pack_bf16x2(l[0], l[1]), pack_bf16x2(l[2], l[3]));
            }
        }
    };

    auto stageA_async = [&](int kt, int s) {
        if constexpr (MODE == 1) {
            const int k0 = kt * BK;
            constexpr int BK8 = BK / 8;
            constexpr int ACH = 2 * BM * BK8;
#pragma unroll
            for (int it = 0; it < ACH / 256; ++it) {
                int idx = tid + it * 256;
                int hl = idx / (ACH / 2);
                int cc = idx % (ACH / 2);
                int row = cc / BK8, kc = cc % BK8;
                int grow = rowBase + row;
                int sz = (grow < M) ? 16 : 0;
                if (grow >= M) grow = M - 1;
                const __nv_bfloat16* src =
                    (hl ? g_zlo : g_zhi) + (size_t)grow * KDIM + k0 + kc * 8;
                cp_async16(sA + s * A_STAGE + hl * (BM * AST) + row * AST + kc * 16, src, sz);
            }
        }
    };

    auto stageB = [&](int kt, int s) {
        const int k0 = kt * BK;
        constexpr int BCH = 2 * BK * (BN / 8);
#pragma unroll
        for (int it = 0; it < BCH / 256; ++it) {
            int c = tid + it * 256;
            int hl = c / (BCH / 2);
            int cc = c % (BCH / 2);
            int row = cc / (BN / 8), nc = cc % (BN / 8);
            const __nv_bfloat16* src =
                (hl ? Bl : Bh) + (size_t)(k0 + row) * BNF + colBase + nc * 8;
            cp_async16(sB + s * B_STAGE + hl * (BK * BROW) + row * BROW + nc * 16, src, 16);
        }
        asm volatile("cp.async.commit_group;");
    };

    ldgA(0);
    stageA_async(0, 0);
    stageB(0, 0);
    for (int kt = 0; kt < KT; ++kt) {
        const int s = kt & 1;
        stsA(s);
        if (kt + 1 < KT) {
            ldgA(kt + 1);
            stageA_async(kt + 1, s ^ 1);
            stageB(kt + 1, s ^ 1);
            asm volatile("cp.async.wait_group 1;");
        } else {
            asm volatile("cp.async.wait_group 0;");
        }
        __syncthreads();

        const int q = lane >> 3;
#pragma unroll
        for (int ks = 0; ks < KS; ++ks) {
            uint32_t a[MI][2][4];
#pragma unroll
            for (int mi = 0; mi < MI; ++mi) {
                int row  = warpM * (MI * 16) + mi * 16 + (q & 1) * 8 + (lane & 7);
                int colb = (ks * 16 + (q >> 1) * 8) * 2;
#pragma unroll
                for (int hl = 0; hl < 2; ++hl)
                    ldsm_x4(a[mi][hl], sA + s * A_STAGE + hl * (BM * AST) + row * AST + colb);
            }
#pragma unroll
            for (int np = 0; np < NT / 2; ++np) {
                uint32_t bq[2][4];
                int krow = ks * 16 + (q & 1) * 8 + (lane & 7);
                int ncol = warpN * (BN / 4) + np * 16 + (q >> 1) * 8;
#pragma unroll
                for (int hl = 0; hl < 2; ++hl)
                    ldsm_x4_t(bq[hl], sB + s * B_STAGE + hl * (BK * BROW) + krow * BROW + ncol * 2);
#pragma unroll
                for (int term = 0; term < 3; ++term) {
                    const int ahl = (term == 2) ? 1 : 0;
                    const int bhl = (term == 1) ? 1 : 0;
#pragma unroll
                    for (int half = 0; half < 2; ++half) {
                        uint32_t bb[2] = {bq[bhl][half * 2], bq[bhl][half * 2 + 1]};
                        const int nt = np * 2 + half;
#pragma unroll
                        for (int mi = 0; mi < MI; ++mi)
                            mma_bf16(acc[mi][nt], a[mi][ahl], bb);
                    }
                }
            }
        }
        __syncthreads();
    }

    // epilogue
#pragma unroll
    for (int mi = 0; mi < MI; ++mi)
#pragma unroll
        for (int nt = 0; nt < NT; ++nt) {
            int col = colBase + warpN * (BN / 4) + nt * 8 + t4 * 2;
            int r0  = rowBase + warpM * (MI * 16) + mi * 16 + g;
            if (r0 < M)
                *(float2*)(C + (size_t)r0 * BNF + col) = make_float2(acc[mi][nt][0], acc[mi][nt][1]);
            int r1 = r0 + 8;
            if (r1 < M)
                *(float2*)(C + (size_t)r1 * BNF + col) = make_float2(acc[mi][nt][2], acc[mi][nt][3]);
        }
}

// ---------------------------------------------------------------------------
// Layer-1 gather aggregation (warp per node, C=256) + bias + relu + bf16 split
// 4-edge batched loads; accumulation order strictly e0,e1,e2,e3 (bitwise
// identical to sequential).
// ---------------------------------------------------------------------------
__global__ __launch_bounds__(256) void gather_agg1_kernel(const float* __restrict__ b1) {
    int node = (blockIdx.x * blockDim.x + threadIdx.x) >> 5;
    int lane = threadIdx.x & 31;
    if (node >= N_NODES) return;

    const float4* h = g_h1;
    float di = g_dinv[node];
    float ws = di * di;
    size_t rb = (size_t)node * 64;
    float4 a0 = h[rb + lane];
    float4 a1 = h[rb + 32 + lane];
    a0.x *= ws; a0.y *= ws; a0.z *= ws; a0.w *= ws;
    a1.x *= ws; a1.y *= ws; a1.z *= ws; a1.w *= ws;

    int beg = g_eoff[node], end = g_eoff[node + 1];
    int k = beg;
    for (; k + 4 <= end; k += 4) {
        int2 e[4];
        e[0] = g_epack[k];     e[1] = g_epack[k + 1];
        e[2] = g_epack[k + 2]; e[3] = g_epack[k + 3];
        float4 v0[4], v1[4];
#pragma unroll
        for (int j = 0; j < 4; ++j) {
            size_t r = (size_t)e[j].x * 64;
            v0[j] = h[r + lane];
            v1[j] = h[r + 32 + lane];
        }
#pragma unroll
        for (int j = 0; j < 4; ++j) {
            float w = __int_as_float(e[j].y);
            a0.x += v0[j].x * w; a0.y += v0[j].y * w;
            a0.z += v0[j].z * w; a0.w += v0[j].w * w;
            a1.x += v1[j].x * w; a1.y += v1[j].y * w;
            a1.z += v1[j].z * w; a1.w += v1[j].w * w;
        }
    }
    for (; k < end; ++k) {
        int2 e0 = g_epack[k];
        float w0 = __int_as_float(e0.y);
        size_t r0 = (size_t)e0.x * 64;
        float4 v00 = h[r0 + lane], v01 = h[r0 + 32 + lane];
        a0.x += v00.x * w0; a0.y += v00.y * w0; a0.z += v00.z * w0; a0.w += v00.w * w0;
        a1.x += v01.x * w0; a1.y += v01.y * w0; a1.z += v01.z * w0; a1.w += v01.w * w0;
    }

    float4 bb0 = ((const float4*)b1)[lane];
    float4 bb1 = ((const float4*)b1)[lane + 32];
    float f0[4] = {fmaxf(a0.x + bb0.x, 0.f), fmaxf(a0.y + bb0.y, 0.f),
                   fmaxf(a0.z + bb0.z, 0.f), fmaxf(a0.w + bb0.w, 0.f)};
    float f1[4] = {fmaxf(a1.x + bb1.x, 0.f), fmaxf(a1.y + bb1.y, 0.f),
                   fmaxf(a1.z + bb1.z, 0.f), fmaxf(a1.w + bb1.w, 0.f)};

    __nv_bfloat162* zh = (__nv_bfloat162*)(g_zhi + (size_t)node * C_HID);
    __nv_bfloat162* zl = (__nv_bfloat162*)(g_zlo + (size_t)node * C_HID);
#pragma unroll
    for (int half = 0; half < 2; ++half) {
        float* f = half ? f1 : f0;
        int idx = 2 * (lane + half * 32);
        __nv_bfloat16 h0 = __float2bfloat16_rn(f[0]);
        __nv_bfloat16 h1v = __float2bfloat16_rn(f[1]);
        __nv_bfloat16 h2v = __float2bfloat16_rn(f[2]);
        __nv_bfloat16 h3 = __float2bfloat16_rn(f[3]);
        zh[idx]     = __nv_bfloat162(h0, h1v);
        zh[idx + 1] = __nv_bfloat162(h2v, h3);
        zl[idx]     = __nv_bfloat162(__float2bfloat16_rn(f[0] - __bfloat162float(h0)),
                                     __float2bfloat16_rn(f[1] - __bfloat162float(h1v)));
        zl[idx + 1] = __nv_bfloat162(__float2bfloat16_rn(f[2] - __bfloat162float(h2v)),
                                     __float2bfloat16_rn(f[3] - __bfloat162float(h3)));
    }
}

// ---------------------------------------------------------------------------
// Layer-2 gather aggregation + bias + row-normalize (warp per node, C=128)
// 4-edge batched loads, ordered accumulation.
// ---------------------------------------------------------------------------
__global__ __launch_bounds__(256) void gather_agg2_kernel(const float* __restrict__ b2,
                                                          float* __restrict__ out) {
    int node = (blockIdx.x * blockDim.x + threadIdx.x) >> 5;
    int lane = threadIdx.x & 31;
    if (node >= N_NODES) return;

    const float4* h = g_h2;
    float di = g_dinv[node];
    float ws = di * di;
    float4 a = h[(size_t)node * 32 + lane];
    a.x *= ws; a.y *= ws; a.z *= ws; a.w *= ws;

    int beg = g_eoff[node], end = g_eoff[node + 1];
    int k = beg;
    for (; k + 4 <= end; k += 4) {
        int2 e[4];
        e[0] = g_epack[k];     e[1] = g_epack[k + 1];
        e[2] = g_epack[k + 2]; e[3] = g_epack[k + 3];
        float4 v[4];
#pragma unroll
        for (int j = 0; j < 4; ++j)
            v[j] = h[(size_t)e[j].x * 32 + lane];
#pragma unroll
        for (int j = 0; j < 4; ++j) {
            float w = __int_as_float(e[j].y);
            a.x += v[j].x * w; a.y += v[j].y * w;
            a.z += v[j].z * w; a.w += v[j].w * w;
        }
    }
    for (; k < end; ++k) {
        int2 e0 = g_epack[k];
        float w0 = __int_as_float(e0.y);
        float4 v0 = h[(size_t)e0.x * 32 + lane];
        a.x += v0.x * w0; a.y += v0.y * w0; a.z += v0.z * w0; a.w += v0.w * w0;
    }

    float4 bb = ((const float4*)b2)[lane];
    a.x += bb.x; a.y += bb.y; a.z += bb.z; a.w += bb.w;
    float s = a.x * a.x + a.y * a.y + a.z * a.z + a.w * a.w;
#pragma unroll
    for (int m = 16; m > 0; m >>= 1) s += __shfl_xor_sync(0xffffffffu, s, m);
    float inv = 1.0f / fmaxf(sqrtf(s), 1e-12f);
    a.x *= inv; a.y *= inv; a.z *= inv; a.w *= inv;
    ((float4*)out)[(size_t)node * 32 + lane] = a;
}

// ---------------------------------------------------------------------------
// Launch: CSR || GEMM1; serial agg1 -> GEMM2 -> agg2 (round-14 topology).
// ---------------------------------------------------------------------------
extern "C" void kernel_launch(void* const* d_in, const int* in_sizes, int n_in,
                              void* d_out, int out_size) {
    const float* x  = (const float*)d_in[0];
    const int*   ei = (const int*)d_in[1];      // int32
    const float* W1 = (const float*)d_in[2];
    const float* b1 = (const float*)d_in[3];
    const float* W2 = (const float*)d_in[4];
    const float* b2 = (const float*)d_in[5];
    float* out = (float*)d_out;

    const int E = in_sizes[1] / 2;
    const int* src = ei;
    const int* dst = ei + E;

    // GEMM1: MI=2,BN=128,BK=32 -> 55296.  GEMM2: MI=1,BN=128,BK=32 -> 45056.
    constexpr int SMEM1 = 2 * (2 * 64 * (32 * 2 + 16) + 2 * 32 * (128 * 2 + 16));
    constexpr int SMEM2 = 2 * (2 * 32 * (32 * 2 + 16) + 2 * 32 * (128 * 2 + 16));

    static cudaStream_t s2 = nullptr;
    static cudaEvent_t  evF = nullptr, evJ = nullptr;
    static bool init_done = false;
    if (!init_done) {
        cudaFuncSetAttribute((const void*)mma_gemm<2, 128, C_IN, 0, 32>,
                             cudaFuncAttributeMaxDynamicSharedMemorySize, SMEM1);
        cudaFuncSetAttribute((const void*)mma_gemm<1, 128, C_HID, 1, 32>,
                             cudaFuncAttributeMaxDynamicSharedMemorySize, SMEM2);
        cudaStreamCreateWithFlags(&s2, cudaStreamNonBlocking);
        cudaEventCreateWithFlags(&evF, cudaEventDisableTiming);
        cudaEventCreateWithFlags(&evJ, cudaEventDisableTiming);
        init_done = true;
    }

    // fork: CSR build chain on s2 (disjoint buffers from GEMM1 path)
    cudaEventRecord(evF, 0);
    cudaStreamWaitEvent(s2, evF, 0);
    zero_deg_kernel<<<(N_NODES + 255) / 256, 256, 0, s2>>>();
    deg_accum_kernel<<<(E + 255) / 256, 256, 0, s2>>>(dst, E);
    scan_kernel<<<1, SCAN_T, 0, s2>>>();
    bucket_kernel<<<(E + 255) / 256, 256, 0, s2>>>(src, dst, E);
    cudaEventRecord(evJ, s2);

    // main stream: weight splits + GEMM1 (concurrent with CSR build)
    split_weights_kernel<<<(W1_N4 + W2_N4 + 255) / 256, 256>>>(W1, W2);
    {
        dim3 grid((N_NODES + 63) / 64, C_HID / 128);
        mma_gemm<2, 128, C_IN, 0, 32><<<grid, 256, SMEM1>>>(x, N_NODES);
    }

    // join: agg1 needs both g_h1 (main) and CSR (s2)
    cudaStreamWaitEvent(0, evJ, 0);

    // serial agg1 -> GEMM2 -> agg2
    gather_agg1_kernel<<<(N_NODES * 32 + 255) / 256, 256>>>(b1);
    {
        dim3 grid((N_NODES + 31) / 32, C_OUT / 128);
        mma_gemm<1, 128, C_HID, 1, 32><<<grid, 256, SMEM2>>>(nullptr, N_NODES);
    }
    gather_agg2_kernel<<<(N_NODES * 32 + 255) / 256, 256>>>(b2, out);
}

// round 17
// speedup vs baseline: 1.1456x; 1.1018x over previous
#include <cuda_runtime.h>
#include <cuda_bf16.h>
#include <cuda_fp16.h>
#include <stdint.h>

// Problem constants (from reference setup_inputs)
#define N_NODES 50000
#define C_IN    1536
#define C_HID   256
#define C_OUT   128
#define E_MAX   1600000

// ---------------------------------------------------------------------------
// Device-global scratch (no allocation allowed)
// ---------------------------------------------------------------------------
__device__ __half g_h1h[N_NODES * C_HID];       // GEMM1 out (fp16)
__device__ __half g_h2h[N_NODES * C_OUT];       // GEMM2 out (fp16)
__device__ float  g_dinv[N_NODES];

// CSR-by-dst edge structure (built per launch)
__device__ int    g_deg   [N_NODES];
__device__ int    g_eoff  [N_NODES + 1];
__device__ int    g_cursor[N_NODES];
__device__ int2   g_epack [E_MAX];              // {src, weight bits} per edge

// bf16 hi/lo splits (K-major weights; z from fused agg1)
__device__ __nv_bfloat16 g_zhi [N_NODES * C_HID];
__device__ __nv_bfloat16 g_zlo [N_NODES * C_HID];
__device__ __nv_bfloat16 g_w1hi[C_IN * C_HID];
__device__ __nv_bfloat16 g_w1lo[C_IN * C_HID];
__device__ __nv_bfloat16 g_w2hi[C_HID * C_OUT];
__device__ __nv_bfloat16 g_w2lo[C_HID * C_OUT];

// ---------------------------------------------------------------------------
// Weight splits: W1 and W2 in ONE launch (f32 -> hi/lo bf16, K-major)
// ---------------------------------------------------------------------------
#define W1_N4 (C_IN * C_HID / 4)    // 98304
#define W2_N4 (C_HID * C_OUT / 4)   // 8192

__global__ void split_weights_kernel(const float* __restrict__ W1,
                                     const float* __restrict__ W2) {
    int i = blockIdx.x * blockDim.x + threadIdx.x;
    if (i >= W1_N4 + W2_N4) return;
    const float4* in;
    __nv_bfloat16 *hi, *lo;
    int j;
    if (i < W1_N4) { in = (const float4*)W1; hi = g_w1hi; lo = g_w1lo; j = i; }
    else           { in = (const float4*)W2; hi = g_w2hi; lo = g_w2lo; j = i - W1_N4; }
    float4 v = in[j];
    float f[4] = {v.x, v.y, v.z, v.w};
    __nv_bfloat16 h[4], l[4];
#pragma unroll
    for (int t = 0; t < 4; ++t) {
        h[t] = __float2bfloat16_rn(f[t]);
        l[t] = __float2bfloat16_rn(f[t] - __bfloat162float(h[t]));
    }
    ((__nv_bfloat162*)hi)[2 * j]     = __nv_bfloat162(h[0], h[1]);
    ((__nv_bfloat162*)hi)[2 * j + 1] = __nv_bfloat162(h[2], h[3]);
    ((__nv_bfloat162*)lo)[2 * j]     = __nv_bfloat162(l[0], l[1]);
    ((__nv_bfloat162*)lo)[2 * j + 1] = __nv_bfloat162(l[2], l[3]);
}

// ---------------------------------------------------------------------------
// degree histogram
// ---------------------------------------------------------------------------
__global__ void zero_deg_kernel() {
    int i = blockIdx.x * blockDim.x + threadIdx.x;
    if (i < N_NODES) g_deg[i] = 0;
}

__global__ void deg_accum_kernel(const int* __restrict__ dst, int E) {
    int i = blockIdx.x * blockDim.x + threadIdx.x;
    if (i < E) {
        unsigned d = (unsigned)dst[i];
        if (d < N_NODES) atomicAdd(&g_deg[d], 1);
    }
}

// ---------------------------------------------------------------------------
// Single-block exclusive scan of g_deg -> g_eoff / g_cursor; also dinv
// ---------------------------------------------------------------------------
#define SCAN_T 1024
__global__ __launch_bounds__(SCAN_T) void scan_kernel() {
    __shared__ int sh[SCAN_T];
    const int tid = threadIdx.x;
    const int PER = (N_NODES + SCAN_T - 1) / SCAN_T;
    const int base = tid * PER;
    int s = 0;
    for (int j = 0; j < PER; ++j) {
        int i = base + j;
        if (i < N_NODES) s += g_deg[i];
    }
    sh[tid] = s;
    __syncthreads();
    for (int off = 1; off < SCAN_T; off <<= 1) {
        int v = (tid >= off) ? sh[tid - off] : 0;
        __syncthreads();
        sh[tid] += v;
        __syncthreads();
    }
    int running = sh[tid] - s;
    for (int j = 0; j < PER; ++j) {
        int i = base + j;
        if (i < N_NODES) {
            int d = g_deg[i];
            g_eoff[i]   = running;
            g_cursor[i] = running;
            g_dinv[i]   = rsqrtf((float)(d + 1));   // +1 self-loop
            running += d;
        }
    }
    if (tid == SCAN_T - 1) g_eoff[N_NODES] = sh[SCAN_T - 1];
}

__global__ void bucket_kernel(const int* __restrict__ src,
                              const int* __restrict__ dst, int E) {
    int e = blockIdx.x * blockDim.x + threadIdx.x;
    if (e >= E) return;
    unsigned s = (unsigned)src[e];
    unsigned d = (unsigned)dst[e];
    if (s >= N_NODES || d >= N_NODES) return;
    int pos = atomicAdd(&g_cursor[d], 1);
    if (pos < E_MAX) {
        float w = g_dinv[s] * g_dinv[d];
        g_epack[pos] = make_int2((int)s, __float_as_int(w));
    }
}

// ---------------------------------------------------------------------------
// PTX helpers
// ---------------------------------------------------------------------------
__device__ __forceinline__ void mma_bf16(float c[4], const uint32_t a[4],
                                         const uint32_t b[2]) {
    asm volatile(
        "mma.sync.aligned.m16n8k16.row.col.f32.bf16.bf16.f32 "
        "{%0,%1,%2,%3}, {%4,%5,%6,%7}, {%8,%9}, {%0,%1,%2,%3};\n"
        : "+f"(c[0]), "+f"(c[1]), "+f"(c[2]), "+f"(c[3])
        : "r"(a[0]), "r"(a[1]), "r"(a[2]), "r"(a[3]), "r"(b[0]), "r"(b[1]));
}

__device__ __forceinline__ void ldsm_x4(uint32_t r[4], uint32_t addr) {
    asm volatile("ldmatrix.sync.aligned.m8n8.x4.shared.b16 {%0,%1,%2,%3}, [%4];"
                 : "=r"(r[0]), "=r"(r[1]), "=r"(r[2]), "=r"(r[3]) : "r"(addr));
}

__device__ __forceinline__ void ldsm_x4_t(uint32_t r[4], uint32_t addr) {
    asm volatile("ldmatrix.sync.aligned.m8n8.x4.trans.shared.b16 {%0,%1,%2,%3}, [%4];"
                 : "=r"(r[0]), "=r"(r[1]), "=r"(r[2]), "=r"(r[3]) : "r"(addr));
}

__device__ __forceinline__ void cp_async16(uint32_t saddr, const void* g, int srcbytes) {
    asm volatile("cp.async.cg.shared.global [%0], [%1], 16, %2;"
                 :: "r"(saddr), "l"(g), "r"(srcbytes));
}

__device__ __forceinline__ void sts_v2(uint32_t saddr, uint32_t a, uint32_t b) {
    asm volatile("st.shared.v2.b32 [%0], {%1, %2};" :: "r"(saddr), "r"(a), "r"(b));
}

__device__ __forceinline__ uint32_t pack_bf16x2(__nv_bfloat16 a, __nv_bfloat16 b) {
    __nv_bfloat162 p(a, b);
    return *(uint32_t*)&p;
}

// unpack 8 fp16 (uint4) -> 8 f32
__device__ __forceinline__ void unpack8h(uint4 u, float* f) {
    const __half2* p = (const __half2*)&u;
#pragma unroll
    for (int i = 0; i < 4; ++i) {
        float2 t = __half22float2(p[i]);
        f[2 * i] = t.x; f[2 * i + 1] = t.y;
    }
}

// unpack 4 fp16 (uint2) -> 4 f32
__device__ __forceinline__ void unpack4h(uint2 u, float* f) {
    const __half2* p = (const __half2*)&u;
#pragma unroll
    for (int i = 0; i < 2; ++i) {
        float2 t = __half22float2(p[i]);
        f[2 * i] = t.x; f[2 * i + 1] = t.y;
    }
}

// ---------------------------------------------------------------------------
// Unified split-bf16 tensor-core GEMM (round-14 proven config), fp16 output.
// 3-term: Ah*Bh + Ah*Bl + Al*Bh, term-outermost MMA order (RAW-chain free).
// GEMM1: MI=2, BN=128, BK=32.  GEMM2: MI=1, BN=128, BK=32.
// MODE 0: A = X (f32, inline hi/lo split via LDG->STS), B = W1 splits, C = g_h1h
// MODE 1: A = z splits (cp.async),                      B = W2 splits, C = g_h2h
// ---------------------------------------------------------------------------
template <int MI, int BN, int KDIM, int MODE, int BK>
__global__ __launch_bounds__(256, 2) void mma_gemm(const float* __restrict__ X, int M) {
    constexpr int BM   = MI * 32;
    constexpr int AST  = BK * 2 + 16;
    constexpr int BROW = BN * 2 + 16;
    constexpr int A_STAGE = 2 * BM * AST;
    constexpr int B_STAGE = 2 * BK * BROW;
    constexpr int NT  = BN / 32;
    constexpr int KT  = KDIM / BK;
    constexpr int KS  = BK / 16;
    constexpr int BNF = MODE ? C_OUT : C_HID;

    const __nv_bfloat16* Bh = MODE ? g_w2hi : g_w1hi;
    const __nv_bfloat16* Bl = MODE ? g_w2lo : g_w1lo;
    __half*              C  = MODE ? g_h2h : g_h1h;

    extern __shared__ char smem[];
    uint32_t sA = (uint32_t)__cvta_generic_to_shared(smem);
    uint32_t sB = sA + 2 * A_STAGE;

    const int tid = threadIdx.x, lane = tid & 31, warp = tid >> 5;
    const int warpM = warp & 1, warpN = warp >> 1;
    const int g = lane >> 2, t4 = lane & 3;
    const int rowBase = blockIdx.x * BM;
    const int colBase = blockIdx.y * BN;

    float acc[MI][NT][4] = {};

    constexpr int BK4 = BK / 4;
    constexpr int AC  = (BM * BK4) / 256;
    float4 areg[AC > 0 ? AC : 1];

    auto ldgA = [&](int kt) {
        if constexpr (MODE == 0) {
            const int k0 = kt * BK;
#pragma unroll
            for (int it = 0; it < AC; ++it) {
                int idx = tid + it * 256;
                int row = idx / BK4;
                int c4  = idx % BK4;
                int grow = rowBase + row;
                if (grow >= M) grow = M - 1;
                areg[it] = *(const float4*)(X + (size_t)grow * KDIM + k0 + c4 * 4);
            }
        }
    };

    auto stsA = [&](int s) {
        if constexpr (MODE == 0) {
#pragma unroll
            for (int it = 0; it < AC; ++it) {
                int idx = tid + it * 256;
                int row = idx / BK4;
                int c4  = idx % BK4;
                float f[4] = {areg[it].x, areg[it].y, areg[it].z, areg[it].w};
                __nv_bfloat16 h[4], l[4];
#pragma unroll
                for (int j = 0; j < 4; ++j) {
                    h[j] = __float2bfloat16_rn(f[j]);
                    l[j] = __float2bfloat16_rn(f[j] - __bfloat162float(h[j]));
                }
                uint32_t base = sA + s * A_STAGE + row * AST + c4 * 8;
                sts_v2(base,            pack_bf16x2(h[0], h[1]), pack_bf16x2(h[2], h[3]));
                sts_v2(base + BM * AST, pack_bf16x2(l[0], l[1]), pack_bf16x2(l[2], l[3]));
            }
        }
    };

    auto stageA_async = [&](int kt, int s) {
        if constexpr (MODE == 1) {
            const int k0 = kt * BK;
            constexpr int BK8 = BK / 8;
            constexpr int ACH = 2 * BM * BK8;
#pragma unroll
            for (int it = 0; it < ACH / 256; ++it) {
                int idx = tid + it * 256;
                int hl = idx / (ACH / 2);
                int cc = idx % (ACH / 2);
                int row = cc / BK8, kc = cc % BK8;
                int grow = rowBase + row;
                int sz = (grow < M) ? 16 : 0;
                if (grow >= M) grow = M - 1;
                const __nv_bfloat16* src =
                    (hl ? g_zlo : g_zhi) + (size_t)grow * KDIM + k0 + kc * 8;
                cp_async16(sA + s * A_STAGE + hl * (BM * AST) + row * AST + kc * 16, src, sz);
            }
        }
    };

    auto stageB = [&](int kt, int s) {
        const int k0 = kt * BK;
        constexpr int BCH = 2 * BK * (BN / 8);
#pragma unroll
        for (int it = 0; it < BCH / 256; ++it) {
            int c = tid + it * 256;
            int hl = c / (BCH / 2);
            int cc = c % (BCH / 2);
            int row = cc / (BN / 8), nc = cc % (BN / 8);
            const __nv_bfloat16* src =
                (hl ? Bl : Bh) + (size_t)(k0 + row) * BNF + colBase + nc * 8;
            cp_async16(sB + s * B_STAGE + hl * (BK * BROW) + row * BROW + nc * 16, src, 16);
        }
        asm volatile("cp.async.commit_group;");
    };

    ldgA(0);
    stageA_async(0, 0);
    stageB(0, 0);
    for (int kt = 0; kt < KT; ++kt) {
        const int s = kt & 1;
        stsA(s);
        if (kt + 1 < KT) {
            ldgA(kt + 1);
            stageA_async(kt + 1, s ^ 1);
            stageB(kt + 1, s ^ 1);
            asm volatile("cp.async.wait_group 1;");
        } else {
            asm volatile("cp.async.wait_group 0;");
        }
        __syncthreads();

        const int q = lane >> 3;
#pragma unroll
        for (int ks = 0; ks < KS; ++ks) {
            uint32_t a[MI][2][4];
#pragma unroll
            for (int mi = 0; mi < MI; ++mi) {
                int row  = warpM * (MI * 16) + mi * 16 + (q & 1) * 8 + (lane & 7);
                int colb = (ks * 16 + (q >> 1) * 8) * 2;
#pragma unroll
                for (int hl = 0; hl < 2; ++hl)
                    ldsm_x4(a[mi][hl], sA + s * A_STAGE + hl * (BM * AST) + row * AST + colb);
            }
#pragma unroll
            for (int np = 0; np < NT / 2; ++np) {
                uint32_t bq[2][4];
                int krow = ks * 16 + (q & 1) * 8 + (lane & 7);
                int ncol = warpN * (BN / 4) + np * 16 + (q >> 1) * 8;
#pragma unroll
                for (int hl = 0; hl < 2; ++hl)
                    ldsm_x4_t(bq[hl], sB + s * B_STAGE + hl * (BK * BROW) + krow * BROW + ncol * 2);
#pragma unroll
                for (int term = 0; term < 3; ++term) {
                    const int ahl = (term == 2) ? 1 : 0;
                    const int bhl = (term == 1) ? 1 : 0;
#pragma unroll
                    for (int half = 0; half < 2; ++half) {
                        uint32_t bb[2] = {bq[bhl][half * 2], bq[bhl][half * 2 + 1]};
                        const int nt = np * 2 + half;
#pragma unroll
                        for (int mi = 0; mi < MI; ++mi)
                            mma_bf16(acc[mi][nt], a[mi][ahl], bb);
                    }
                }
            }
        }
        __syncthreads();
    }

    // epilogue: write fp16
#pragma unroll
    for (int mi = 0; mi < MI; ++mi)
#pragma unroll
        for (int nt = 0; nt < NT; ++nt) {
            int col = colBase + warpN * (BN / 4) + nt * 8 + t4 * 2;
            int r0  = rowBase + warpM * (MI * 16) + mi * 16 + g;
            if (r0 < M)
                *(__half2*)(C + (size_t)r0 * BNF + col) =
                    __float22half2_rn(make_float2(acc[mi][nt][0], acc[mi][nt][1]));
            int r1 = r0 + 8;
            if (r1 < M)
                *(__half2*)(C + (size_t)r1 * BNF + col) =
                    __float22half2_rn(make_float2(acc[mi][nt][2], acc[mi][nt][3]));
        }
}

// ---------------------------------------------------------------------------
// Layer-1 gather aggregation (warp per node, C=256, fp16 gathers).
// Lane owns 8 contiguous channels [8*lane, 8*lane+8). 4-edge batching; per-
// channel accumulation order identical to sequential edge order.
// ---------------------------------------------------------------------------
__global__ __launch_bounds__(256) void gather_agg1_kernel(const float* __restrict__ b1) {
    int node = (blockIdx.x * blockDim.x + threadIdx.x) >> 5;
    int lane = threadIdx.x & 31;
    if (node >= N_NODES) return;

    const __half* h = g_h1h;
    float di = g_dinv[node];
    float ws = di * di;

    float a[8];
    {
        uint4 sv = *(const uint4*)(h + (size_t)node * C_HID + lane * 8);
        float f[8]; unpack8h(sv, f);
#pragma unroll
        for (int j = 0; j < 8; ++j) a[j] = f[j] * ws;
    }

    int beg = g_eoff[node], end = g_eoff[node + 1];
    int k = beg;
    for (; k + 4 <= end; k += 4) {
        int2 e[4];
        e[0] = g_epack[k];     e[1] = g_epack[k + 1];
        e[2] = g_epack[k + 2]; e[3] = g_epack[k + 3];
        uint4 v[4];
#pragma unroll
        for (int j = 0; j < 4; ++j)
            v[j] = *(const uint4*)(h + (size_t)e[j].x * C_HID + lane * 8);
#pragma unroll
        for (int j = 0; j < 4; ++j) {
            float w = __int_as_float(e[j].y);
            float f[8]; unpack8h(v[j], f);
#pragma unroll
            for (int c = 0; c < 8; ++c) a[c] += f[c] * w;
        }
    }
    for (; k < end; ++k) {
        int2 e0 = g_epack[k];
        float w = __int_as_float(e0.y);
        uint4 v = *(const uint4*)(h + (size_t)e0.x * C_HID + lane * 8);
        float f[8]; unpack8h(v, f);
#pragma unroll
        for (int c = 0; c < 8; ++c) a[c] += f[c] * w;
    }

    // bias + relu
    float4 bb0 = ((const float4*)b1)[lane * 2];
    float4 bb1 = ((const float4*)b1)[lane * 2 + 1];
    float bf[8] = {bb0.x, bb0.y, bb0.z, bb0.w, bb1.x, bb1.y, bb1.z, bb1.w};
    float f[8];
#pragma unroll
    for (int c = 0; c < 8; ++c) f[c] = fmaxf(a[c] + bf[c], 0.f);

    // bf16 hi/lo split, 16B stores
    uint32_t hw[4], lw[4];
#pragma unroll
    for (int p = 0; p < 4; ++p) {
        __nv_bfloat16 h0 = __float2bfloat16_rn(f[2 * p]);
        __nv_bfloat16 h1 = __float2bfloat16_rn(f[2 * p + 1]);
        hw[p] = pack_bf16x2(h0, h1);
        lw[p] = pack_bf16x2(__float2bfloat16_rn(f[2 * p]     - __bfloat162float(h0)),
                            __float2bfloat16_rn(f[2 * p + 1] - __bfloat162float(h1)));
    }
    size_t zoff = (size_t)node * C_HID + lane * 8;
    *(uint4*)(g_zhi + zoff) = make_uint4(hw[0], hw[1], hw[2], hw[3]);
    *(uint4*)(g_zlo + zoff) = make_uint4(lw[0], lw[1], lw[2], lw[3]);
}

// ---------------------------------------------------------------------------
// Layer-2 gather aggregation + bias + row-normalize (warp per node, C=128,
// fp16 gathers). Lane owns channels [4*lane, 4*lane+4).
// ---------------------------------------------------------------------------
__global__ __launch_bounds__(256) void gather_agg2_kernel(const float* __restrict__ b2,
                                                          float* __restrict__ out) {
    int node = (blockIdx.x * blockDim.x + threadIdx.x) >> 5;
    int lane = threadIdx.x & 31;
    if (node >= N_NODES) return;

    const __half* h = g_h2h;
    float di = g_dinv[node];
    float ws = di * di;

    float a[4];
    {
        uint2 sv = *(const uint2*)(h + (size_t)node * C_OUT + lane * 4);
        float f[4]; unpack4h(sv, f);
#pragma unroll
        for (int j = 0; j < 4; ++j) a[j] = f[j] * ws;
    }

    int beg = g_eoff[node], end = g_eoff[node + 1];
    int k = beg;
    for (; k + 4 <= end; k += 4) {
        int2 e[4];
        e[0] = g_epack[k];     e[1] = g_epack[k + 1];
        e[2] = g_epack[k + 2]; e[3] = g_epack[k + 3];
        uint2 v[4];
#pragma unroll
        for (int j = 0; j < 4; ++j)
            v[j] = *(const uint2*)(h + (size_t)e[j].x * C_OUT + lane * 4);
#pragma unroll
        for (int j = 0; j < 4; ++j) {
            float w = __int_as_float(e[j].y);
            float f[4]; unpack4h(v[j], f);
#pragma unroll
            for (int c = 0; c < 4; ++c) a[c] += f[c] * w;
        }
    }
    for (; k < end; ++k) {
        int2 e0 = g_epack[k];
        float w = __int_as_float(e0.y);
        uint2 v = *(const uint2*)(h + (size_t)e0.x * C_OUT + lane * 4);
        float f[4]; unpack4h(v, f);
#pragma unroll
        for (int c = 0; c < 4; ++c) a[c] += f[c] * w;
    }

    float4 bb = ((const float4*)b2)[lane];
    a[0] += bb.x; a[1] += bb.y; a[2] += bb.z; a[3] += bb.w;
    float s = a[0] * a[0] + a[1] * a[1] + a[2] * a[2] + a[3] * a[3];
#pragma unroll
    for (int m = 16; m > 0; m >>= 1) s += __shfl_xor_sync(0xffffffffu, s, m);
    float inv = 1.0f / fmaxf(sqrtf(s), 1e-12f);
    ((float4*)out)[(size_t)node * 32 + lane] =
        make_float4(a[0] * inv, a[1] * inv, a[2] * inv, a[3] * inv);
}

// ---------------------------------------------------------------------------
// Launch: CSR || GEMM1; serial agg1 -> GEMM2 -> agg2 (round-14 topology).
// ---------------------------------------------------------------------------
extern "C" void kernel_launch(void* const* d_in, const int* in_sizes, int n_in,
                              void* d_out, int out_size) {
    const float* x  = (const float*)d_in[0];
    const int*   ei = (const int*)d_in[1];      // int32
    const float* W1 = (const float*)d_in[2];
    const float* b1 = (const float*)d_in[3];
    const float* W2 = (const float*)d_in[4];
    const float* b2 = (const float*)d_in[5];
    float* out = (float*)d_out;

    const int E = in_sizes[1] / 2;
    const int* src = ei;
    const int* dst = ei + E;

    constexpr int SMEM1 = 2 * (2 * 64 * (32 * 2 + 16) + 2 * 32 * (128 * 2 + 16));  // 55296
    constexpr int SMEM2 = 2 * (2 * 32 * (32 * 2 + 16) + 2 * 32 * (128 * 2 + 16)); // 45056

    static cudaStream_t s2 = nullptr;
    static cudaEvent_t  evF = nullptr, evJ = nullptr;
    static bool init_done = false;
    if (!init_done) {
        cudaFuncSetAttribute((const void*)mma_gemm<2, 128, C_IN, 0, 32>,
                             cudaFuncAttributeMaxDynamicSharedMemorySize, SMEM1);
        cudaFuncSetAttribute((const void*)mma_gemm<1, 128, C_HID, 1, 32>,
                             cudaFuncAttributeMaxDynamicSharedMemorySize, SMEM2);
        cudaStreamCreateWithFlags(&s2, cudaStreamNonBlocking);
        cudaEventCreateWithFlags(&evF, cudaEventDisableTiming);
        cudaEventCreateWithFlags(&evJ, cudaEventDisableTiming);
        init_done = true;
    }

    // fork: CSR build chain on s2 (disjoint buffers from GEMM1 path)
    cudaEventRecord(evF, 0);
    cudaStreamWaitEvent(s2, evF, 0);
    zero_deg_kernel<<<(N_NODES + 255) / 256, 256, 0, s2>>>();
    deg_accum_kernel<<<(E + 255) / 256, 256, 0, s2>>>(dst, E);
    scan_kernel<<<1, SCAN_T, 0, s2>>>();
    bucket_kernel<<<(E + 255) / 256, 256, 0, s2>>>(src, dst, E);
    cudaEventRecord(evJ, s2);

    // main stream: weight splits + GEMM1 (concurrent with CSR build)
    split_weights_kernel<<<(W1_N4 + W2_N4 + 255) / 256, 256>>>(W1, W2);
    {
        dim3 grid((N_NODES + 63) / 64, C_HID / 128);
        mma_gemm<2, 128, C_IN, 0, 32><<<grid, 256, SMEM1>>>(x, N_NODES);
    }

    // join: agg1 needs both g_h1h (main) and CSR (s2)
    cudaStreamWaitEvent(0, evJ, 0);

    // serial agg1 -> GEMM2 -> agg2
    gather_agg1_kernel<<<(N_NODES * 32 + 255) / 256, 256>>>(b1);
    {
        dim3 grid((N_NODES + 31) / 32, C_OUT / 128);
        mma_gemm<1, 128, C_HID, 1, 32><<<grid, 256, SMEM2>>>(nullptr, N_NODES);
    }
    gather_agg2_kernel<<<(N_NODES * 32 + 255) / 256, 256>>>(b2, out);
}